// round 2
// baseline (speedup 1.0000x reference)
#include <cuda_runtime.h>
#include <math.h>

// ---------------- Problem constants ----------------
#define FRAMESN 256
#define PATCHES 64
#define DIMD    512
#define HEADS   8
#define DH      64
#define DFF     1024
#define KP      128          // Linformer projected length
#define T1      257          // temporal seq len (cls + 256 frames)
#define B1      64           // temporal batch (patches)
#define T2      65           // spatial seq len (cls + 64 patches)
#define B2      256          // spatial batch (frames)
#define NTOK1   (B1*T1)      // 16448
#define NTOK2   (B2*T2)      // 16640
#define LDQKV   (3*DIMD)     // 1536

// ---------------- Scratch (device globals; no runtime allocation) --------
__device__ float g_xt[NTOK1*DIMD];                 // temporal-arranged input
__device__ float g_qkv[NTOK2*LDQKV];               // QKV (reused temporal/spatial)
__device__ float g_scores[B1*HEADS*T1*T1];         // attention scores (reused)
__device__ float g_attn[NTOK2*DIMD];               // attention output (pre-Wo)
__device__ float g_y1[NTOK1*DIMD];                 // temporal block output
__device__ float g_ys[NTOK2*DIMD];                 // spatial-arranged input
__device__ float g_kvp[B2*HEADS*2*KP*DH];          // Linformer projected K,V
__device__ float g_ffh[NTOK2*DFF];                 // FFN hidden

__device__ __forceinline__ float gelu_exact(float v) {
    return 0.5f * v * (1.0f + erff(v * 0.70710678118654752f));
}

// ---------------- Rearrange kernels ----------------
// temporal: seq s = patch, token t: t==0 -> cls, else x[1 + (t-1)*64 + s]
__global__ void build_xt_kernel(const float* __restrict__ x, float* __restrict__ xt) {
    int token = blockIdx.x;
    int s = token / T1, t = token % T1;
    size_t src_tok = (t == 0) ? 0 : (size_t)(1 + (size_t)(t - 1) * PATCHES + s);
    const float4* src = (const float4*)(x + src_tok * DIMD);
    float4* dst = (float4*)(xt + (size_t)token * DIMD);
    dst[threadIdx.x] = src[threadIdx.x];
}

// spatial: seq i = frame, token j: j==0 -> cls2[i%64] = y1[(i%64)*257],
// else y1[(j-1)*257 + 1 + i]
__global__ void build_ys_kernel(const float* __restrict__ y1, float* __restrict__ ys) {
    int token = blockIdx.x;
    int i = token / T2, j = token % T2;
    size_t src_tok = (j == 0) ? (size_t)(i % 64) * T1
                              : (size_t)(j - 1) * T1 + 1 + i;
    const float4* src = (const float4*)(y1 + src_tok * DIMD);
    float4* dst = (float4*)(ys + (size_t)token * DIMD);
    dst[threadIdx.x] = src[threadIdx.x];
}

// ---------------- Main GEMM: C = A(MxK) * B(KxN) [+ epilogue] ----------------
// Requires M%64==0, N%64==0, K%16==0 (all call sites satisfy this).
// epi: 0 none, 1 +R, 2 +bias then gelu, 3 +bias +R
__global__ void gemm_big(const float* __restrict__ A, const float* __restrict__ B,
                         float* __restrict__ C, const float* __restrict__ bias,
                         const float* __restrict__ R,
                         int M, int N, int K, int epi)
{
    __shared__ float sA[64][17];
    __shared__ float sB[16][64];
    int tid = threadIdx.x;
    int tx = tid & 15, ty = tid >> 4;
    int row0 = blockIdx.y * 64;
    int col0 = blockIdx.x * 64;

    float acc[4][4];
#pragma unroll
    for (int i = 0; i < 4; i++)
#pragma unroll
        for (int j = 0; j < 4; j++) acc[i][j] = 0.f;

    for (int k0 = 0; k0 < K; k0 += 16) {
#pragma unroll
        for (int l = 0; l < 4; l++) {
            int idx = tid + l * 256;
            int r = idx >> 4, c = idx & 15;
            sA[r][c] = A[(size_t)(row0 + r) * K + k0 + c];
        }
#pragma unroll
        for (int l = 0; l < 4; l++) {
            int idx = tid + l * 256;
            int r = idx >> 6, c = idx & 63;
            sB[r][c] = B[(size_t)(k0 + r) * N + col0 + c];
        }
        __syncthreads();
#pragma unroll
        for (int kk = 0; kk < 16; kk++) {
            float ra[4];
#pragma unroll
            for (int i = 0; i < 4; i++) ra[i] = sA[ty * 4 + i][kk];
            float4 rb = *(const float4*)&sB[kk][tx * 4];
#pragma unroll
            for (int i = 0; i < 4; i++) {
                acc[i][0] += ra[i] * rb.x;
                acc[i][1] += ra[i] * rb.y;
                acc[i][2] += ra[i] * rb.z;
                acc[i][3] += ra[i] * rb.w;
            }
        }
        __syncthreads();
    }

    float4 bb = make_float4(0.f, 0.f, 0.f, 0.f);
    if (epi >= 2) bb = *(const float4*)&bias[col0 + tx * 4];
#pragma unroll
    for (int i = 0; i < 4; i++) {
        int r = row0 + ty * 4 + i;
        size_t off = (size_t)r * N + col0 + tx * 4;
        float4 v = make_float4(acc[i][0], acc[i][1], acc[i][2], acc[i][3]);
        if (epi >= 2) { v.x += bb.x; v.y += bb.y; v.z += bb.z; v.w += bb.w; }
        if (epi == 2) {
            v.x = gelu_exact(v.x); v.y = gelu_exact(v.y);
            v.z = gelu_exact(v.z); v.w = gelu_exact(v.w);
        }
        if (epi == 1 || epi == 3) {
            float4 rr = *(const float4*)&R[off];
            v.x += rr.x; v.y += rr.y; v.z += rr.z; v.w += rr.w;
        }
        *(float4*)&C[off] = v;
    }
}

// ---------------- Batched NT GEMM, K=64: C = scale * A * B^T ----------------
// Per batch z: zo = z>>3, zi = z&7; ptr += zo*so + zi*si
__global__ void gemm_nt_k64(const float* __restrict__ Ab, int lda, long sao, long sai,
                            const float* __restrict__ Bb, int ldb, long sbo, long sbi,
                            float* __restrict__ Cb, int ldc, long sco, long sci,
                            int M, int N, float scale)
{
    int z = blockIdx.z, zo = z >> 3, zi = z & 7;
    const float* A = Ab + (size_t)zo * sao + (size_t)zi * sai;
    const float* B = Bb + (size_t)zo * sbo + (size_t)zi * sbi;
    float* C = Cb + (size_t)zo * sco + (size_t)zi * sci;

    __shared__ float sA[32][65];
    __shared__ float sB[32][65];
    int tid = threadIdx.x;
    int tx = tid & 15, ty = tid >> 4;
    int row0 = blockIdx.y * 32;
    int col0 = blockIdx.x * 32;

#pragma unroll
    for (int l = 0; l < 8; l++) {
        int idx = tid + l * 256;
        int r = idx >> 6, c = idx & 63;
        sA[r][c] = (row0 + r < M) ? A[(size_t)(row0 + r) * lda + c] : 0.f;
        sB[r][c] = (col0 + r < N) ? B[(size_t)(col0 + r) * ldb + c] : 0.f;
    }
    __syncthreads();

    float a00 = 0.f, a01 = 0.f, a10 = 0.f, a11 = 0.f;
#pragma unroll
    for (int k = 0; k < 64; k++) {
        float r0 = sA[ty * 2][k], r1 = sA[ty * 2 + 1][k];
        float c0 = sB[tx * 2][k], c1 = sB[tx * 2 + 1][k];
        a00 += r0 * c0; a01 += r0 * c1;
        a10 += r1 * c0; a11 += r1 * c1;
    }
    int r = row0 + ty * 2, c = col0 + tx * 2;
    if (r < M) {
        if (c < N)     C[(size_t)r * ldc + c]     = a00 * scale;
        if (c + 1 < N) C[(size_t)r * ldc + c + 1] = a01 * scale;
    }
    if (r + 1 < M) {
        if (c < N)     C[(size_t)(r + 1) * ldc + c]     = a10 * scale;
        if (c + 1 < N) C[(size_t)(r + 1) * ldc + c + 1] = a11 * scale;
    }
}

// ---------------- Batched NN GEMM: C = A(MxK) * B(KxN) ----------------
__global__ void gemm_nn_b(const float* __restrict__ Ab, int lda, long sao, long sai,
                          const float* __restrict__ Bb, int ldb, long sbo, long sbi,
                          float* __restrict__ Cb, int ldc, long sco, long sci,
                          int M, int N, int K)
{
    int z = blockIdx.z, zo = z >> 3, zi = z & 7;
    const float* A = Ab + (size_t)zo * sao + (size_t)zi * sai;
    const float* B = Bb + (size_t)zo * sbo + (size_t)zi * sbi;
    float* C = Cb + (size_t)zo * sco + (size_t)zi * sci;

    __shared__ float sA[32][17];
    __shared__ float sB[16][33];
    int tid = threadIdx.x;
    int tx = tid & 15, ty = tid >> 4;
    int row0 = blockIdx.y * 32;
    int col0 = blockIdx.x * 32;

    float a00 = 0.f, a01 = 0.f, a10 = 0.f, a11 = 0.f;
    for (int k0 = 0; k0 < K; k0 += 16) {
#pragma unroll
        for (int l = 0; l < 2; l++) {
            int idx = tid + l * 256;
            int r = idx >> 4, c = idx & 15;
            sA[r][c] = (row0 + r < M && k0 + c < K)
                     ? A[(size_t)(row0 + r) * lda + k0 + c] : 0.f;
        }
        {
            int idx = tid;
            int r = idx >> 5, c = idx & 31;
            sB[r][c] = (k0 + r < K && col0 + c < N)
                     ? B[(size_t)(k0 + r) * ldb + col0 + c] : 0.f;
            idx = tid + 256; r = idx >> 5; c = idx & 31;
            sB[r][c] = (k0 + r < K && col0 + c < N)
                     ? B[(size_t)(k0 + r) * ldb + col0 + c] : 0.f;
        }
        __syncthreads();
#pragma unroll
        for (int kk = 0; kk < 16; kk++) {
            float r0 = sA[ty * 2][kk], r1 = sA[ty * 2 + 1][kk];
            float c0 = sB[kk][tx * 2], c1 = sB[kk][tx * 2 + 1];
            a00 += r0 * c0; a01 += r0 * c1;
            a10 += r1 * c0; a11 += r1 * c1;
        }
        __syncthreads();
    }
    int r = row0 + ty * 2, c = col0 + tx * 2;
    if (r < M && c < N)         C[(size_t)r * ldc + c]           = a00;
    if (r < M && c + 1 < N)     C[(size_t)r * ldc + c + 1]       = a01;
    if (r + 1 < M && c < N)     C[(size_t)(r + 1) * ldc + c]     = a10;
    if (r + 1 < M && c + 1 < N) C[(size_t)(r + 1) * ldc + c + 1] = a11;
}

// ---------------- Softmax over rows of length L ----------------
__global__ void softmax_kernel(float* __restrict__ S, int L) {
    float* row = S + (size_t)blockIdx.x * L;
    __shared__ float red[256];
    int tid = threadIdx.x;
    float m = -1e30f;
    for (int i = tid; i < L; i += 256) m = fmaxf(m, row[i]);
    red[tid] = m; __syncthreads();
    for (int s = 128; s > 0; s >>= 1) {
        if (tid < s) red[tid] = fmaxf(red[tid], red[tid + s]);
        __syncthreads();
    }
    m = red[0]; __syncthreads();
    float sum = 0.f;
    for (int i = tid; i < L; i += 256) {
        float e = __expf(row[i] - m);
        row[i] = e; sum += e;
    }
    red[tid] = sum; __syncthreads();
    for (int s = 128; s > 0; s >>= 1) {
        if (tid < s) red[tid] += red[tid + s];
        __syncthreads();
    }
    float inv = 1.f / red[0];
    for (int i = tid; i < L; i += 256) row[i] *= inv;
}

// ---------------- Linformer E-projection ----------------
// For batch b = i*8+h and kv in {0(K),1(V)}:
//   dst[kk][c] = sum_j qkv[i*65*1536 + j*1536 + 512 + kv*512 + h*64 + c] * E[j][kk]
// grid.x = 4096 (b*2 + kv), grid.y = 2 (kk half)
__global__ void eproj_kernel(const float* __restrict__ qkv, const float* __restrict__ E,
                             float* __restrict__ kvp)
{
    int z = blockIdx.x;
    int b = z >> 1, kv = z & 1;
    int i = b >> 3, h = b & 7;
    const float* src = qkv + (size_t)i * T2 * LDQKV + h * DH + DIMD + kv * DIMD;
    float* dst = kvp + (size_t)b * 2 * KP * DH + (size_t)kv * KP * DH;

    __shared__ float ssrc[T2][DH];    // 65x64
    __shared__ float sE[T2][64];      // 65x64 slice of E
    int half = blockIdx.y;            // which 64-wide kk half

    for (int idx = threadIdx.x; idx < T2 * DH; idx += 256) {
        int j = idx >> 6, c = idx & 63;
        ssrc[j][c] = src[(size_t)j * LDQKV + c];
        sE[j][c]   = E[(size_t)j * KP + half * 64 + c];
    }
    __syncthreads();

    int c = threadIdx.x & 63;
    int kkq = threadIdx.x >> 6;       // 0..3
    float acc[16];
#pragma unroll
    for (int q = 0; q < 16; q++) acc[q] = 0.f;
    for (int j = 0; j < T2; j++) {
        float s = ssrc[j][c];
#pragma unroll
        for (int q = 0; q < 16; q++) acc[q] += s * sE[j][kkq * 16 + q];
    }
    int kk0 = half * 64 + kkq * 16;
#pragma unroll
    for (int q = 0; q < 16; q++) dst[(size_t)(kk0 + q) * DH + c] = acc[q];
}

// ---------------- Launch ----------------
static float* sym_addr(const void* s) {
    void* p = nullptr;
    cudaGetSymbolAddress(&p, s);
    return (float*)p;
}

extern "C" void kernel_launch(void* const* d_in, const int* in_sizes, int n_in,
                              void* d_out, int out_size)
{
    (void)in_sizes; (void)n_in; (void)out_size;
    const float* x      = (const float*)d_in[0];
    const float* Wqkv_t = (const float*)d_in[1];
    const float* Wo_t   = (const float*)d_in[2];
    const float* Wqkv_s = (const float*)d_in[3];
    const float* Wo_s   = (const float*)d_in[4];
    const float* E      = (const float*)d_in[5];
    const float* W1     = (const float*)d_in[6];
    const float* b1     = (const float*)d_in[7];
    const float* W2     = (const float*)d_in[8];
    const float* b2     = (const float*)d_in[9];
    float* out = (float*)d_out;

    float* xt  = sym_addr(g_xt);
    float* qkv = sym_addr(g_qkv);
    float* sc  = sym_addr(g_scores);
    float* att = sym_addr(g_attn);
    float* y1  = sym_addr(g_y1);
    float* ys  = sym_addr(g_ys);
    float* kvp = sym_addr(g_kvp);
    float* ffh = sym_addr(g_ffh);

    const float scale = 0.125f;  // 1/sqrt(64)

    // ---- temporal ----
    build_xt_kernel<<<NTOK1, 128>>>(x, xt);

    gemm_big<<<dim3(LDQKV / 64, NTOK1 / 64), 256>>>(
        xt, Wqkv_t, qkv, nullptr, nullptr, NTOK1, LDQKV, DIMD, 0);

    // scores: per z=(s*8+h): Q off = s*T1*1536 + h*64, K off same + 512
    gemm_nt_k64<<<dim3(9, 9, B1 * HEADS), 256>>>(
        qkv,       LDQKV, (long)T1 * LDQKV, 64,
        qkv + 512, LDQKV, (long)T1 * LDQKV, 64,
        sc, T1, (long)8 * T1 * T1, (long)T1 * T1,
        T1, T1, scale);

    softmax_kernel<<<B1 * HEADS * T1, 256>>>(sc, T1);

    // att @ V
    gemm_nn_b<<<dim3(2, 9, B1 * HEADS), 256>>>(
        sc, T1, (long)8 * T1 * T1, (long)T1 * T1,
        qkv + 1024, LDQKV, (long)T1 * LDQKV, 64,
        att, DIMD, (long)T1 * DIMD, 64,
        T1, DH, T1);

    // y1 = att @ Wo_t + xt
    gemm_big<<<dim3(DIMD / 64, NTOK1 / 64), 256>>>(
        att, Wo_t, y1, nullptr, xt, NTOK1, DIMD, DIMD, 1);

    // ---- spatial ----
    build_ys_kernel<<<NTOK2, 128>>>(y1, ys);

    gemm_big<<<dim3(LDQKV / 64, NTOK2 / 64), 256>>>(
        ys, Wqkv_s, qkv, nullptr, nullptr, NTOK2, LDQKV, DIMD, 0);

    // Linformer K', V'
    eproj_kernel<<<dim3(B2 * HEADS * 2, 2), 256>>>(qkv, E, kvp);

    // scores: Q(i,h) vs K'(i,h): Q off = i*T2*1536 + h*64; K' off = z*KP*DH*2
    gemm_nt_k64<<<dim3(4, 3, B2 * HEADS), 256>>>(
        qkv, LDQKV, (long)T2 * LDQKV, 64,
        kvp, DH, (long)8 * 2 * KP * DH, (long)2 * KP * DH,
        sc, KP, (long)8 * T2 * KP, (long)T2 * KP,
        T2, KP, scale);

    softmax_kernel<<<B2 * HEADS * T2, 256>>>(sc, KP);

    // att @ V'
    gemm_nn_b<<<dim3(2, 3, B2 * HEADS), 256>>>(
        sc, KP, (long)8 * T2 * KP, (long)T2 * KP,
        kvp + KP * DH, DH, (long)8 * 2 * KP * DH, (long)2 * KP * DH,
        att, DIMD, (long)T2 * DIMD, 64,
        T2, DH, KP);

    // out = att @ Wo_s + ys   (spatial block output lives in d_out)
    gemm_big<<<dim3(DIMD / 64, NTOK2 / 64), 256>>>(
        att, Wo_s, out, nullptr, ys, NTOK2, DIMD, DIMD, 1);

    // ---- FFN ----
    gemm_big<<<dim3(DFF / 64, NTOK2 / 64), 256>>>(
        out, W1, ffh, b1, nullptr, NTOK2, DFF, DIMD, 2);

    gemm_big<<<dim3(DIMD / 64, NTOK2 / 64), 256>>>(
        ffh, W2, out, b2, out, NTOK2, DIMD, DFF, 3);
}

// round 7
// speedup vs baseline: 1.5675x; 1.5675x over previous
#include <cuda_runtime.h>
#include <mma.h>
#include <math.h>

using namespace nvcuda;

// ---------------- Problem constants ----------------
#define FRAMESN 256
#define PATCHES 64
#define DIMD    512
#define HEADS   8
#define DH      64
#define DFF     1024
#define KP      128          // Linformer projected length
#define T1      257          // temporal seq len (cls + 256 frames)
#define B1      64           // temporal batch (patches)
#define T2      65           // spatial seq len (cls + 64 patches)
#define B2      256          // spatial batch (frames)
#define NTOK1   (B1*T1)      // 16448
#define NTOK2   (B2*T2)      // 16640
#define LDQKV   (3*DIMD)     // 1536

// ---------------- Scratch (device globals; no runtime allocation) --------
__device__ float g_xt[NTOK1*DIMD];
__device__ float g_qkv[NTOK2*LDQKV];
__device__ float g_scores[B1*HEADS*T1*T1];
__device__ float g_attn[NTOK2*DIMD];
__device__ float g_y1[NTOK1*DIMD];
__device__ float g_ys[NTOK2*DIMD];
__device__ float g_kvp[B2*HEADS*2*KP*DH];
__device__ float g_ffh[NTOK2*DFF];

__device__ __forceinline__ float gelu_exact(float v) {
    return 0.5f * v * (1.0f + erff(v * 0.70710678118654752f));
}

// ---------------- Rearrange kernels ----------------
__global__ void build_xt_kernel(const float* __restrict__ x, float* __restrict__ xt) {
    int token = blockIdx.x;
    int s = token / T1, t = token % T1;
    size_t src_tok = (t == 0) ? 0 : (size_t)(1 + (size_t)(t - 1) * PATCHES + s);
    const float4* src = (const float4*)(x + src_tok * DIMD);
    float4* dst = (float4*)(xt + (size_t)token * DIMD);
    dst[threadIdx.x] = src[threadIdx.x];
}

__global__ void build_ys_kernel(const float* __restrict__ y1, float* __restrict__ ys) {
    int token = blockIdx.x;
    int i = token / T2, j = token % T2;
    size_t src_tok = (j == 0) ? (size_t)(i % 64) * T1
                              : (size_t)(j - 1) * T1 + 1 + i;
    const float4* src = (const float4*)(y1 + src_tok * DIMD);
    float4* dst = (float4*)(ys + (size_t)token * DIMD);
    dst[threadIdx.x] = src[threadIdx.x];
}

// ================= TF32 tensor-core GEMM (dense) =================
// C = A(MxK,row) * B(KxN,row) [+ epilogue]. M%64==0, N%64==0, K%32==0.
// epi: 0 none, 1 +R, 2 +bias->gelu, 3 +bias+R
// 256 threads = 8 warps; block tile 64x64, warp tile 16x32, BK=32.
#define SA_LD 36
#define SB_LD 68
#define SC_LD 68
__global__ void gemm_tc(const float* __restrict__ A, const float* __restrict__ B,
                        float* __restrict__ C, const float* __restrict__ bias,
                        const float* __restrict__ R,
                        int M, int N, int K, int epi)
{
    __shared__ float sA[64 * SA_LD];
    __shared__ float sB[32 * SB_LD];
    __shared__ float sC[64 * SC_LD];

    int tid = threadIdx.x;
    int warp = tid >> 5;
    int wm = warp >> 1;          // 0..3  (M direction, 16 rows each)
    int wn = warp & 1;           // 0..1  (N direction, 32 cols each)
    int row0 = blockIdx.y * 64;
    int col0 = blockIdx.x * 64;

    wmma::fragment<wmma::accumulator, 16, 16, 8, float> c0, c1;
    wmma::fill_fragment(c0, 0.f);
    wmma::fill_fragment(c1, 0.f);

    for (int k0 = 0; k0 < K; k0 += 32) {
        // load A tile 64x32 (512 float4, 2 per thread)
#pragma unroll
        for (int l = 0; l < 2; l++) {
            int idx = tid + l * 256;
            int r = idx >> 3, c4 = idx & 7;
            float4 v = *(const float4*)&A[(size_t)(row0 + r) * K + k0 + c4 * 4];
            *(float4*)&sA[r * SA_LD + c4 * 4] = v;
        }
        // load B tile 32x64 (512 float4, 2 per thread)
#pragma unroll
        for (int l = 0; l < 2; l++) {
            int idx = tid + l * 256;
            int r = idx >> 4, c4 = idx & 15;
            float4 v = *(const float4*)&B[(size_t)(k0 + r) * N + col0 + c4 * 4];
            *(float4*)&sB[r * SB_LD + c4 * 4] = v;
        }
        __syncthreads();
#pragma unroll
        for (int kk = 0; kk < 32; kk += 8) {
            wmma::fragment<wmma::matrix_a, 16, 16, 8, wmma::precision::tf32, wmma::row_major> a;
            wmma::fragment<wmma::matrix_b, 16, 16, 8, wmma::precision::tf32, wmma::row_major> b0, b1;
            wmma::load_matrix_sync(a, &sA[(wm * 16) * SA_LD + kk], SA_LD);
            wmma::load_matrix_sync(b0, &sB[kk * SB_LD + wn * 32], SB_LD);
            wmma::load_matrix_sync(b1, &sB[kk * SB_LD + wn * 32 + 16], SB_LD);
#pragma unroll
            for (int i = 0; i < a.num_elements; i++)  a.x[i]  = wmma::__float_to_tf32(a.x[i]);
#pragma unroll
            for (int i = 0; i < b0.num_elements; i++) b0.x[i] = wmma::__float_to_tf32(b0.x[i]);
#pragma unroll
            for (int i = 0; i < b1.num_elements; i++) b1.x[i] = wmma::__float_to_tf32(b1.x[i]);
            wmma::mma_sync(c0, a, b0, c0);
            wmma::mma_sync(c1, a, b1, c1);
        }
        __syncthreads();
    }

    wmma::store_matrix_sync(&sC[(wm * 16) * SC_LD + wn * 32], c0, SC_LD, wmma::mem_row_major);
    wmma::store_matrix_sync(&sC[(wm * 16) * SC_LD + wn * 32 + 16], c1, SC_LD, wmma::mem_row_major);
    __syncthreads();

    // epilogue: 64x64 tile = 1024 float4, 4 per thread
#pragma unroll
    for (int l = 0; l < 4; l++) {
        int idx = tid + l * 256;
        int r = idx >> 4, c4 = idx & 15;
        size_t off = (size_t)(row0 + r) * N + col0 + c4 * 4;
        float4 v = *(float4*)&sC[r * SC_LD + c4 * 4];
        if (epi >= 2) {
            float4 bb = *(const float4*)&bias[col0 + c4 * 4];
            v.x += bb.x; v.y += bb.y; v.z += bb.z; v.w += bb.w;
        }
        if (epi == 2) {
            v.x = gelu_exact(v.x); v.y = gelu_exact(v.y);
            v.z = gelu_exact(v.z); v.w = gelu_exact(v.w);
        }
        if (epi == 1 || epi == 3) {
            float4 rr = *(const float4*)&R[off];
            v.x += rr.x; v.y += rr.y; v.z += rr.z; v.w += rr.w;
        }
        *(float4*)&C[off] = v;
    }
}

// ================= TF32 batched NT scores: C = scale * A(Mx64) * B(Nx64)^T ===
// Per batch z: zo=z>>3, zi=z&7. Block tile 64x64, K=64 fixed.
__global__ void scores_tc(const float* __restrict__ Ab, int lda, long sao, long sai,
                          const float* __restrict__ Bb, int ldb, long sbo, long sbi,
                          float* __restrict__ Cb, int ldc, long sco, long sci,
                          int M, int N, float scale)
{
    __shared__ float sm[2 * 64 * SB_LD];
    float* sQ = sm;
    float* sK = sm + 64 * SB_LD;

    int z = blockIdx.z, zo = z >> 3, zi = z & 7;
    const float* A = Ab + (size_t)zo * sao + (size_t)zi * sai;
    const float* B = Bb + (size_t)zo * sbo + (size_t)zi * sbi;
    float* C = Cb + (size_t)zo * sco + (size_t)zi * sci;

    int tid = threadIdx.x;
    int warp = tid >> 5;
    int wm = warp >> 1, wn = warp & 1;
    int row0 = blockIdx.y * 64;
    int col0 = blockIdx.x * 64;

    // load 64x64 Q and K tiles (each 1024 f4, 4 per thread), zero-pad OOB rows
#pragma unroll
    for (int l = 0; l < 4; l++) {
        int idx = tid + l * 256;
        int r = idx >> 4, c4 = idx & 15;
        float4 zq = make_float4(0.f, 0.f, 0.f, 0.f);
        float4 v = (row0 + r < M) ? *(const float4*)&A[(size_t)(row0 + r) * lda + c4 * 4] : zq;
        *(float4*)&sQ[r * SB_LD + c4 * 4] = v;
        float4 w = (col0 + r < N) ? *(const float4*)&B[(size_t)(col0 + r) * ldb + c4 * 4] : zq;
        *(float4*)&sK[r * SB_LD + c4 * 4] = w;
    }
    __syncthreads();

    wmma::fragment<wmma::accumulator, 16, 16, 8, float> c0, c1;
    wmma::fill_fragment(c0, 0.f);
    wmma::fill_fragment(c1, 0.f);
#pragma unroll
    for (int kk = 0; kk < 64; kk += 8) {
        wmma::fragment<wmma::matrix_a, 16, 16, 8, wmma::precision::tf32, wmma::row_major> a;
        wmma::fragment<wmma::matrix_b, 16, 16, 8, wmma::precision::tf32, wmma::col_major> b0, b1;
        wmma::load_matrix_sync(a, &sQ[(wm * 16) * SB_LD + kk], SB_LD);
        wmma::load_matrix_sync(b0, &sK[(wn * 32) * SB_LD + kk], SB_LD);
        wmma::load_matrix_sync(b1, &sK[(wn * 32 + 16) * SB_LD + kk], SB_LD);
#pragma unroll
        for (int i = 0; i < a.num_elements; i++)  a.x[i]  = wmma::__float_to_tf32(a.x[i]);
#pragma unroll
        for (int i = 0; i < b0.num_elements; i++) b0.x[i] = wmma::__float_to_tf32(b0.x[i]);
#pragma unroll
        for (int i = 0; i < b1.num_elements; i++) b1.x[i] = wmma::__float_to_tf32(b1.x[i]);
        wmma::mma_sync(c0, a, b0, c0);
        wmma::mma_sync(c1, a, b1, c1);
    }
    __syncthreads();

    // reuse sQ region as output staging
    wmma::store_matrix_sync(&sQ[(wm * 16) * SB_LD + wn * 32], c0, SB_LD, wmma::mem_row_major);
    wmma::store_matrix_sync(&sQ[(wm * 16) * SB_LD + wn * 32 + 16], c1, SB_LD, wmma::mem_row_major);
    __syncthreads();

    for (int idx = tid; idx < 64 * 64; idx += 256) {
        int r = idx >> 6, c = idx & 63;
        if (row0 + r < M && col0 + c < N)
            C[(size_t)(row0 + r) * ldc + col0 + c] = sQ[r * SB_LD + c] * scale;
    }
}

// ================= TF32 batched NN AV: C(Mx64) = A(MxL) * B(Lx64) =========
__global__ void av_tc(const float* __restrict__ Ab, int lda, long sao, long sai,
                      const float* __restrict__ Bb, int ldb, long sbo, long sbi,
                      float* __restrict__ Cb, int ldc, long sco, long sci,
                      int M, int L)
{
    __shared__ float sP[64 * SA_LD];
    __shared__ float sV[32 * SB_LD];
    __shared__ float sC[64 * SC_LD];

    int z = blockIdx.z, zo = z >> 3, zi = z & 7;
    const float* A = Ab + (size_t)zo * sao + (size_t)zi * sai;
    const float* B = Bb + (size_t)zo * sbo + (size_t)zi * sbi;
    float* C = Cb + (size_t)zo * sco + (size_t)zi * sci;

    int tid = threadIdx.x;
    int warp = tid >> 5;
    int wm = warp >> 1, wn = warp & 1;
    int row0 = blockIdx.y * 64;

    wmma::fragment<wmma::accumulator, 16, 16, 8, float> c0, c1;
    wmma::fill_fragment(c0, 0.f);
    wmma::fill_fragment(c1, 0.f);

    for (int k0 = 0; k0 < L; k0 += 32) {
        // P tile 64x32 guarded
#pragma unroll
        for (int l = 0; l < 8; l++) {
            int idx = tid + l * 256;
            int r = idx >> 5, c = idx & 31;
            sP[r * SA_LD + c] = (row0 + r < M && k0 + c < L)
                              ? A[(size_t)(row0 + r) * lda + k0 + c] : 0.f;
        }
        // V tile 32x64 guarded rows
#pragma unroll
        for (int l = 0; l < 8; l++) {
            int idx = tid + l * 256;
            int r = idx >> 6, c = idx & 63;
            sV[r * SB_LD + c] = (k0 + r < L)
                              ? B[(size_t)(k0 + r) * ldb + c] : 0.f;
        }
        __syncthreads();
#pragma unroll
        for (int kk = 0; kk < 32; kk += 8) {
            wmma::fragment<wmma::matrix_a, 16, 16, 8, wmma::precision::tf32, wmma::row_major> a;
            wmma::fragment<wmma::matrix_b, 16, 16, 8, wmma::precision::tf32, wmma::row_major> b0, b1;
            wmma::load_matrix_sync(a, &sP[(wm * 16) * SA_LD + kk], SA_LD);
            wmma::load_matrix_sync(b0, &sV[kk * SB_LD + wn * 32], SB_LD);
            wmma::load_matrix_sync(b1, &sV[kk * SB_LD + wn * 32 + 16], SB_LD);
#pragma unroll
            for (int i = 0; i < a.num_elements; i++)  a.x[i]  = wmma::__float_to_tf32(a.x[i]);
#pragma unroll
            for (int i = 0; i < b0.num_elements; i++) b0.x[i] = wmma::__float_to_tf32(b0.x[i]);
#pragma unroll
            for (int i = 0; i < b1.num_elements; i++) b1.x[i] = wmma::__float_to_tf32(b1.x[i]);
            wmma::mma_sync(c0, a, b0, c0);
            wmma::mma_sync(c1, a, b1, c1);
        }
        __syncthreads();
    }

    wmma::store_matrix_sync(&sC[(wm * 16) * SC_LD + wn * 32], c0, SC_LD, wmma::mem_row_major);
    wmma::store_matrix_sync(&sC[(wm * 16) * SC_LD + wn * 32 + 16], c1, SC_LD, wmma::mem_row_major);
    __syncthreads();

    for (int idx = tid; idx < 64 * 64; idx += 256) {
        int r = idx >> 6, c = idx & 63;
        if (row0 + r < M)
            C[(size_t)(row0 + r) * ldc + c] = sC[r * SC_LD + c];
    }
}

// ---------------- Warp-per-row softmax ----------------
__global__ void softmax_warp(float* __restrict__ S, int L, int rows) {
    int row = blockIdx.x * 8 + (threadIdx.x >> 5);
    if (row >= rows) return;
    int lane = threadIdx.x & 31;
    float* r = S + (size_t)row * L;

    float m = -1e30f;
    for (int i = lane; i < L; i += 32) m = fmaxf(m, r[i]);
#pragma unroll
    for (int s = 16; s > 0; s >>= 1) m = fmaxf(m, __shfl_xor_sync(0xffffffffu, m, s));

    float sum = 0.f;
    for (int i = lane; i < L; i += 32) {
        float e = __expf(r[i] - m);
        r[i] = e; sum += e;
    }
#pragma unroll
    for (int s = 16; s > 0; s >>= 1) sum += __shfl_xor_sync(0xffffffffu, sum, s);

    float inv = 1.f / sum;
    for (int i = lane; i < L; i += 32) r[i] *= inv;
}

// ---------------- Linformer E-projection (fp32, small) ----------------
__global__ void eproj_kernel(const float* __restrict__ qkv, const float* __restrict__ E,
                             float* __restrict__ kvp)
{
    int z = blockIdx.x;
    int b = z >> 1, kv = z & 1;
    int i = b >> 3, h = b & 7;
    const float* src = qkv + (size_t)i * T2 * LDQKV + h * DH + DIMD + kv * DIMD;
    float* dst = kvp + (size_t)b * 2 * KP * DH + (size_t)kv * KP * DH;

    __shared__ float ssrc[T2][DH];
    __shared__ float sE[T2][64];
    int half = blockIdx.y;

    for (int idx = threadIdx.x; idx < T2 * DH; idx += 256) {
        int j = idx >> 6, c = idx & 63;
        ssrc[j][c] = src[(size_t)j * LDQKV + c];
        sE[j][c]   = E[(size_t)j * KP + half * 64 + c];
    }
    __syncthreads();

    int c = threadIdx.x & 63;
    int kkq = threadIdx.x >> 6;
    float acc[16];
#pragma unroll
    for (int q = 0; q < 16; q++) acc[q] = 0.f;
    for (int j = 0; j < T2; j++) {
        float s = ssrc[j][c];
#pragma unroll
        for (int q = 0; q < 16; q++) acc[q] += s * sE[j][kkq * 16 + q];
    }
    int kk0 = half * 64 + kkq * 16;
#pragma unroll
    for (int q = 0; q < 16; q++) dst[(size_t)(kk0 + q) * DH + c] = acc[q];
}

// ---------------- Launch ----------------
static float* sym_addr(const void* s) {
    void* p = nullptr;
    cudaGetSymbolAddress(&p, s);
    return (float*)p;
}

extern "C" void kernel_launch(void* const* d_in, const int* in_sizes, int n_in,
                              void* d_out, int out_size)
{
    (void)in_sizes; (void)n_in; (void)out_size;
    const float* x      = (const float*)d_in[0];
    const float* Wqkv_t = (const float*)d_in[1];
    const float* Wo_t   = (const float*)d_in[2];
    const float* Wqkv_s = (const float*)d_in[3];
    const float* Wo_s   = (const float*)d_in[4];
    const float* E      = (const float*)d_in[5];
    const float* W1     = (const float*)d_in[6];
    const float* b1     = (const float*)d_in[7];
    const float* W2     = (const float*)d_in[8];
    const float* b2     = (const float*)d_in[9];
    float* out = (float*)d_out;

    float* xt  = sym_addr(g_xt);
    float* qkv = sym_addr(g_qkv);
    float* sc  = sym_addr(g_scores);
    float* att = sym_addr(g_attn);
    float* y1  = sym_addr(g_y1);
    float* ys  = sym_addr(g_ys);
    float* kvp = sym_addr(g_kvp);
    float* ffh = sym_addr(g_ffh);

    const float scale = 0.125f;  // 1/sqrt(64)

    // ---- temporal ----
    build_xt_kernel<<<NTOK1, 128>>>(x, xt);

    gemm_tc<<<dim3(LDQKV / 64, NTOK1 / 64), 256>>>(
        xt, Wqkv_t, qkv, nullptr, nullptr, NTOK1, LDQKV, DIMD, 0);

    scores_tc<<<dim3(5, 5, B1 * HEADS), 256>>>(
        qkv,       LDQKV, (long)T1 * LDQKV, 64,
        qkv + 512, LDQKV, (long)T1 * LDQKV, 64,
        sc, T1, (long)8 * T1 * T1, (long)T1 * T1,
        T1, T1, scale);

    softmax_warp<<<(B1 * HEADS * T1 + 7) / 8, 256>>>(sc, T1, B1 * HEADS * T1);

    av_tc<<<dim3(1, 5, B1 * HEADS), 256>>>(
        sc, T1, (long)8 * T1 * T1, (long)T1 * T1,
        qkv + 1024, LDQKV, (long)T1 * LDQKV, 64,
        att, DIMD, (long)T1 * DIMD, 64,
        T1, T1);

    gemm_tc<<<dim3(DIMD / 64, NTOK1 / 64), 256>>>(
        att, Wo_t, y1, nullptr, xt, NTOK1, DIMD, DIMD, 1);

    // ---- spatial ----
    build_ys_kernel<<<NTOK2, 128>>>(y1, ys);

    gemm_tc<<<dim3(LDQKV / 64, NTOK2 / 64), 256>>>(
        ys, Wqkv_s, qkv, nullptr, nullptr, NTOK2, LDQKV, DIMD, 0);

    eproj_kernel<<<dim3(B2 * HEADS * 2, 2), 256>>>(qkv, E, kvp);

    scores_tc<<<dim3(2, 2, B2 * HEADS), 256>>>(
        qkv, LDQKV, (long)T2 * LDQKV, 64,
        kvp, DH, (long)8 * 2 * KP * DH, (long)2 * KP * DH,
        sc, KP, (long)8 * T2 * KP, (long)T2 * KP,
        T2, KP, scale);

    softmax_warp<<<(B2 * HEADS * T2 + 7) / 8, 256>>>(sc, KP, B2 * HEADS * T2);

    av_tc<<<dim3(1, 2, B2 * HEADS), 256>>>(
        sc, KP, (long)8 * T2 * KP, (long)T2 * KP,
        kvp + KP * DH, DH, (long)8 * 2 * KP * DH, (long)2 * KP * DH,
        att, DIMD, (long)T2 * DIMD, 64,
        T2, KP);

    gemm_tc<<<dim3(DIMD / 64, NTOK2 / 64), 256>>>(
        att, Wo_s, out, nullptr, ys, NTOK2, DIMD, DIMD, 1);

    // ---- FFN ----
    gemm_tc<<<dim3(DFF / 64, NTOK2 / 64), 256>>>(
        out, W1, ffh, b1, nullptr, NTOK2, DFF, DIMD, 2);

    gemm_tc<<<dim3(DIMD / 64, NTOK2 / 64), 256>>>(
        ffh, W2, out, b2, out, NTOK2, DIMD, DFF, 3);
}

// round 12
// speedup vs baseline: 1.8143x; 1.1574x over previous
#include <cuda_runtime.h>
#include <mma.h>
#include <math.h>
#include <stdint.h>

using namespace nvcuda;

// ---------------- Problem constants ----------------
#define FRAMESN 256
#define PATCHES 64
#define DIMD    512
#define HEADS   8
#define DH      64
#define DFF     1024
#define KP      128          // Linformer projected length
#define T1      257          // temporal seq len (cls + 256 frames)
#define B1      64           // temporal batch (patches)
#define T2      65           // spatial seq len (cls + 64 patches)
#define B2      256          // spatial batch (frames)
#define NTOK1   (B1*T1)      // 16448
#define NTOK1P  16512        // padded to 129*128 for guard-free dense GEMM
#define NTOK2   (B2*T2)      // 16640
#define LDQKV   (3*DIMD)     // 1536

// ---------------- Scratch (device globals; no runtime allocation) --------
__device__ float g_xt[NTOK1P*DIMD];
__device__ float g_qkv[NTOK2*LDQKV];
__device__ float g_scores[B1*HEADS*T1*T1];
__device__ float g_attn[NTOK2*DIMD];
__device__ float g_y1[NTOK1P*DIMD];
__device__ float g_ys[NTOK2*DIMD];
__device__ float g_kvp[B2*HEADS*2*KP*DH];
__device__ float g_ffh[NTOK2*DFF];

__device__ __forceinline__ float gelu_exact(float v) {
    return 0.5f * v * (1.0f + erff(v * 0.70710678118654752f));
}

// ---------------- cp.async helpers ----------------
__device__ __forceinline__ void cp16(void* dst, const void* src) {
    uint32_t d = (uint32_t)__cvta_generic_to_shared(dst);
    asm volatile("cp.async.cg.shared.global [%0], [%1], 16;\n" :: "r"(d), "l"(src));
}
__device__ __forceinline__ void cp_commit() {
    asm volatile("cp.async.commit_group;\n");
}
template <int NW>
__device__ __forceinline__ void cp_wait() {
    asm volatile("cp.async.wait_group %0;\n" :: "n"(NW));
}

// ---------------- Rearrange kernels ----------------
__global__ void build_xt_kernel(const float* __restrict__ x, float* __restrict__ xt) {
    int token = blockIdx.x;
    float4* dst = (float4*)(xt + (size_t)token * DIMD);
    int s = token / T1, t = token % T1;
    if (s >= B1) {                       // padding rows -> zero
        dst[threadIdx.x] = make_float4(0.f, 0.f, 0.f, 0.f);
        return;
    }
    size_t src_tok = (t == 0) ? 0 : (size_t)(1 + (size_t)(t - 1) * PATCHES + s);
    const float4* src = (const float4*)(x + src_tok * DIMD);
    dst[threadIdx.x] = src[threadIdx.x];
}

__global__ void build_ys_kernel(const float* __restrict__ y1, float* __restrict__ ys) {
    int token = blockIdx.x;
    int i = token / T2, j = token % T2;
    size_t src_tok = (j == 0) ? (size_t)(i % 64) * T1
                              : (size_t)(j - 1) * T1 + 1 + i;
    const float4* src = (const float4*)(y1 + src_tok * DIMD);
    float4* dst = (float4*)(ys + (size_t)token * DIMD);
    dst[threadIdx.x] = src[threadIdx.x];
}

// ================= TF32 tensor-core GEMM (dense, 128x128, cp.async 2-stage) ===
// C = A(MxK,row) * B(KxN,row) [+ epilogue]. M%128==0, N%128==0, K%16==0.
// epi: 0 none, 1 +R, 2 +bias->gelu, 3 +bias+R
// 256 threads = 8 warps (2x4); warp tile 64x32; BK=16.
#define BMD 128
#define BND 128
#define BKD 16
#define ALD 20     // 16 + 4 pad (row = 80B, 16B-aligned)
#define BLD 132    // 128 + 4 pad (row = 528B, 16B-aligned)

__global__ void __launch_bounds__(256, 2)
gemm_tc128(const float* __restrict__ A, const float* __restrict__ B,
           float* __restrict__ C, const float* __restrict__ bias,
           const float* __restrict__ R, int N, int K, int epi)
{
    __shared__ float sA[2][BMD * ALD];
    __shared__ float sB[2][BKD * BLD];

    int tid = threadIdx.x;
    int warp = tid >> 5, lane = tid & 31;
    int wm = warp >> 2, wn = warp & 3;          // warp grid 2x4
    int row0 = blockIdx.y * BMD;
    int col0 = blockIdx.x * BND;

    const float* Aptr = A + (size_t)row0 * K;
    const float* Bptr = B + col0;

    wmma::fragment<wmma::accumulator, 16, 16, 8, float> acc[4][2];
#pragma unroll
    for (int i = 0; i < 4; i++)
#pragma unroll
        for (int j = 0; j < 2; j++) wmma::fill_fragment(acc[i][j], 0.f);

    // per-thread load coordinates
    // A tile 128x16 = 512 float4: idx -> r=idx>>2, c4=idx&3
    // B tile 16x128 = 512 float4: idx -> r=idx>>5, c4=idx&31
    const int a_r0 = (tid      ) >> 2, a_c0 = (tid      ) & 3;
    const int a_r1 = (tid + 256) >> 2, a_c1 = (tid + 256) & 3;
    const int b_r0 = (tid      ) >> 5, b_c0 = (tid      ) & 31;
    const int b_r1 = (tid + 256) >> 5, b_c1 = (tid + 256) & 31;

    const int nch = K / BKD;

    // prologue: chunk 0 -> buf 0
    {
        cp16(&sA[0][a_r0 * ALD + a_c0 * 4], Aptr + (size_t)a_r0 * K + a_c0 * 4);
        cp16(&sA[0][a_r1 * ALD + a_c1 * 4], Aptr + (size_t)a_r1 * K + a_c1 * 4);
        cp16(&sB[0][b_r0 * BLD + b_c0 * 4], Bptr + (size_t)b_r0 * N + b_c0 * 4);
        cp16(&sB[0][b_r1 * BLD + b_c1 * 4], Bptr + (size_t)b_r1 * N + b_c1 * 4);
        cp_commit();
    }

    for (int it = 0; it < nch; it++) {
        int buf = it & 1;
        if (it + 1 < nch) {
            int k0 = (it + 1) * BKD;
            int nb = buf ^ 1;
            cp16(&sA[nb][a_r0 * ALD + a_c0 * 4], Aptr + (size_t)a_r0 * K + k0 + a_c0 * 4);
            cp16(&sA[nb][a_r1 * ALD + a_c1 * 4], Aptr + (size_t)a_r1 * K + k0 + a_c1 * 4);
            cp16(&sB[nb][b_r0 * BLD + b_c0 * 4], Bptr + (size_t)(k0 + b_r0) * N + b_c0 * 4);
            cp16(&sB[nb][b_r1 * BLD + b_c1 * 4], Bptr + (size_t)(k0 + b_r1) * N + b_c1 * 4);
            cp_commit();
            cp_wait<1>();
        } else {
            cp_wait<0>();
        }
        __syncthreads();

#pragma unroll
        for (int ks = 0; ks < 2; ks++) {
            wmma::fragment<wmma::matrix_a, 16, 16, 8, wmma::precision::tf32, wmma::row_major> af[4];
            wmma::fragment<wmma::matrix_b, 16, 16, 8, wmma::precision::tf32, wmma::row_major> bf[2];
#pragma unroll
            for (int i = 0; i < 4; i++) {
                wmma::load_matrix_sync(af[i], &sA[buf][(wm * 64 + i * 16) * ALD + ks * 8], ALD);
#pragma unroll
                for (int e = 0; e < af[i].num_elements; e++)
                    af[i].x[e] = wmma::__float_to_tf32(af[i].x[e]);
            }
#pragma unroll
            for (int j = 0; j < 2; j++) {
                wmma::load_matrix_sync(bf[j], &sB[buf][(ks * 8) * BLD + wn * 32 + j * 16], BLD);
#pragma unroll
                for (int e = 0; e < bf[j].num_elements; e++)
                    bf[j].x[e] = wmma::__float_to_tf32(bf[j].x[e]);
            }
#pragma unroll
            for (int i = 0; i < 4; i++)
#pragma unroll
                for (int j = 0; j < 2; j++)
                    wmma::mma_sync(acc[i][j], af[i], bf[j], acc[i][j]);
        }
        __syncthreads();
    }

    // ---- epilogue: per-warp 16x16 patch through smem ----
    float* patch = &sA[0][warp * 16 * ALD];   // 8 warps * 320 floats = 2560 <= BMD*ALD
    int pr = lane >> 1;
    int pc = (lane & 1) * 8;
#pragma unroll
    for (int i = 0; i < 4; i++) {
#pragma unroll
        for (int j = 0; j < 2; j++) {
            wmma::store_matrix_sync(patch, acc[i][j], ALD, wmma::mem_row_major);
            __syncwarp();
            int grow = row0 + wm * 64 + i * 16 + pr;
            int gcol = col0 + wn * 32 + j * 16 + pc;
#pragma unroll
            for (int h = 0; h < 2; h++) {
                float4 v = *(float4*)&patch[pr * ALD + pc + h * 4];
                size_t off = (size_t)grow * N + gcol + h * 4;
                if (epi >= 2) {
                    float4 bb = *(const float4*)&bias[gcol + h * 4];
                    v.x += bb.x; v.y += bb.y; v.z += bb.z; v.w += bb.w;
                }
                if (epi == 2) {
                    v.x = gelu_exact(v.x); v.y = gelu_exact(v.y);
                    v.z = gelu_exact(v.z); v.w = gelu_exact(v.w);
                }
                if (epi == 1 || epi == 3) {
                    float4 rr = *(const float4*)&R[off];
                    v.x += rr.x; v.y += rr.y; v.z += rr.z; v.w += rr.w;
                }
                *(float4*)&C[off] = v;
            }
            __syncwarp();
        }
    }
}

// ================= TF32 batched NT scores: C = scale * A(Mx64) * B(Nx64)^T ===
#define SA_LD 36
#define SB_LD 68
#define SC_LD 68
__global__ void scores_tc(const float* __restrict__ Ab, int lda, long sao, long sai,
                          const float* __restrict__ Bb, int ldb, long sbo, long sbi,
                          float* __restrict__ Cb, int ldc, long sco, long sci,
                          int M, int N, float scale)
{
    __shared__ float sm[2 * 64 * SB_LD];
    float* sQ = sm;
    float* sK = sm + 64 * SB_LD;

    int z = blockIdx.z, zo = z >> 3, zi = z & 7;
    const float* A = Ab + (size_t)zo * sao + (size_t)zi * sai;
    const float* B = Bb + (size_t)zo * sbo + (size_t)zi * sbi;
    float* C = Cb + (size_t)zo * sco + (size_t)zi * sci;

    int tid = threadIdx.x;
    int warp = tid >> 5;
    int wm = warp >> 1, wn = warp & 1;
    int row0 = blockIdx.y * 64;
    int col0 = blockIdx.x * 64;

#pragma unroll
    for (int l = 0; l < 4; l++) {
        int idx = tid + l * 256;
        int r = idx >> 4, c4 = idx & 15;
        float4 zq = make_float4(0.f, 0.f, 0.f, 0.f);
        float4 v = (row0 + r < M) ? *(const float4*)&A[(size_t)(row0 + r) * lda + c4 * 4] : zq;
        *(float4*)&sQ[r * SB_LD + c4 * 4] = v;
        float4 w = (col0 + r < N) ? *(const float4*)&B[(size_t)(col0 + r) * ldb + c4 * 4] : zq;
        *(float4*)&sK[r * SB_LD + c4 * 4] = w;
    }
    __syncthreads();

    wmma::fragment<wmma::accumulator, 16, 16, 8, float> c0, c1;
    wmma::fill_fragment(c0, 0.f);
    wmma::fill_fragment(c1, 0.f);
#pragma unroll
    for (int kk = 0; kk < 64; kk += 8) {
        wmma::fragment<wmma::matrix_a, 16, 16, 8, wmma::precision::tf32, wmma::row_major> a;
        wmma::fragment<wmma::matrix_b, 16, 16, 8, wmma::precision::tf32, wmma::col_major> b0, b1;
        wmma::load_matrix_sync(a, &sQ[(wm * 16) * SB_LD + kk], SB_LD);
        wmma::load_matrix_sync(b0, &sK[(wn * 32) * SB_LD + kk], SB_LD);
        wmma::load_matrix_sync(b1, &sK[(wn * 32 + 16) * SB_LD + kk], SB_LD);
#pragma unroll
        for (int i = 0; i < a.num_elements; i++)  a.x[i]  = wmma::__float_to_tf32(a.x[i]);
#pragma unroll
        for (int i = 0; i < b0.num_elements; i++) b0.x[i] = wmma::__float_to_tf32(b0.x[i]);
#pragma unroll
        for (int i = 0; i < b1.num_elements; i++) b1.x[i] = wmma::__float_to_tf32(b1.x[i]);
        wmma::mma_sync(c0, a, b0, c0);
        wmma::mma_sync(c1, a, b1, c1);
    }
    __syncthreads();

    wmma::store_matrix_sync(&sQ[(wm * 16) * SB_LD + wn * 32], c0, SB_LD, wmma::mem_row_major);
    wmma::store_matrix_sync(&sQ[(wm * 16) * SB_LD + wn * 32 + 16], c1, SB_LD, wmma::mem_row_major);
    __syncthreads();

    for (int idx = tid; idx < 64 * 64; idx += 256) {
        int r = idx >> 6, c = idx & 63;
        if (row0 + r < M && col0 + c < N)
            C[(size_t)(row0 + r) * ldc + col0 + c] = sQ[r * SB_LD + c] * scale;
    }
}

// ================= TF32 batched NN AV: C(Mx64) = A(MxL) * B(Lx64) =========
__global__ void av_tc(const float* __restrict__ Ab, int lda, long sao, long sai,
                      const float* __restrict__ Bb, int ldb, long sbo, long sbi,
                      float* __restrict__ Cb, int ldc, long sco, long sci,
                      int M, int L)
{
    __shared__ float sP[64 * SA_LD];
    __shared__ float sV[32 * SB_LD];
    __shared__ float sC[64 * SC_LD];

    int z = blockIdx.z, zo = z >> 3, zi = z & 7;
    const float* A = Ab + (size_t)zo * sao + (size_t)zi * sai;
    const float* B = Bb + (size_t)zo * sbo + (size_t)zi * sbi;
    float* C = Cb + (size_t)zo * sco + (size_t)zi * sci;

    int tid = threadIdx.x;
    int warp = tid >> 5;
    int wm = warp >> 1, wn = warp & 1;
    int row0 = blockIdx.y * 64;

    wmma::fragment<wmma::accumulator, 16, 16, 8, float> c0, c1;
    wmma::fill_fragment(c0, 0.f);
    wmma::fill_fragment(c1, 0.f);

    for (int k0 = 0; k0 < L; k0 += 32) {
#pragma unroll
        for (int l = 0; l < 8; l++) {
            int idx = tid + l * 256;
            int r = idx >> 5, c = idx & 31;
            sP[r * SA_LD + c] = (row0 + r < M && k0 + c < L)
                              ? A[(size_t)(row0 + r) * lda + k0 + c] : 0.f;
        }
#pragma unroll
        for (int l = 0; l < 8; l++) {
            int idx = tid + l * 256;
            int r = idx >> 6, c = idx & 63;
            sV[r * SB_LD + c] = (k0 + r < L)
                              ? B[(size_t)(k0 + r) * ldb + c] : 0.f;
        }
        __syncthreads();
#pragma unroll
        for (int kk = 0; kk < 32; kk += 8) {
            wmma::fragment<wmma::matrix_a, 16, 16, 8, wmma::precision::tf32, wmma::row_major> a;
            wmma::fragment<wmma::matrix_b, 16, 16, 8, wmma::precision::tf32, wmma::row_major> b0, b1;
            wmma::load_matrix_sync(a, &sP[(wm * 16) * SA_LD + kk], SA_LD);
            wmma::load_matrix_sync(b0, &sV[kk * SB_LD + wn * 32], SB_LD);
            wmma::load_matrix_sync(b1, &sV[kk * SB_LD + wn * 32 + 16], SB_LD);
#pragma unroll
            for (int i = 0; i < a.num_elements; i++)  a.x[i]  = wmma::__float_to_tf32(a.x[i]);
#pragma unroll
            for (int i = 0; i < b0.num_elements; i++) b0.x[i] = wmma::__float_to_tf32(b0.x[i]);
#pragma unroll
            for (int i = 0; i < b1.num_elements; i++) b1.x[i] = wmma::__float_to_tf32(b1.x[i]);
            wmma::mma_sync(c0, a, b0, c0);
            wmma::mma_sync(c1, a, b1, c1);
        }
        __syncthreads();
    }

    wmma::store_matrix_sync(&sC[(wm * 16) * SC_LD + wn * 32], c0, SC_LD, wmma::mem_row_major);
    wmma::store_matrix_sync(&sC[(wm * 16) * SC_LD + wn * 32 + 16], c1, SC_LD, wmma::mem_row_major);
    __syncthreads();

    for (int idx = tid; idx < 64 * 64; idx += 256) {
        int r = idx >> 6, c = idx & 63;
        if (row0 + r < M)
            C[(size_t)(row0 + r) * ldc + c] = sC[r * SC_LD + c];
    }
}

// ---------------- Warp-per-row softmax ----------------
__global__ void softmax_warp(float* __restrict__ S, int L, int rows) {
    int row = blockIdx.x * 8 + (threadIdx.x >> 5);
    if (row >= rows) return;
    int lane = threadIdx.x & 31;
    float* r = S + (size_t)row * L;

    float m = -1e30f;
    for (int i = lane; i < L; i += 32) m = fmaxf(m, r[i]);
#pragma unroll
    for (int s = 16; s > 0; s >>= 1) m = fmaxf(m, __shfl_xor_sync(0xffffffffu, m, s));

    float sum = 0.f;
    for (int i = lane; i < L; i += 32) {
        float e = __expf(r[i] - m);
        r[i] = e; sum += e;
    }
#pragma unroll
    for (int s = 16; s > 0; s >>= 1) sum += __shfl_xor_sync(0xffffffffu, sum, s);

    float inv = 1.f / sum;
    for (int i = lane; i < L; i += 32) r[i] *= inv;
}

// ---------------- Linformer E-projection (fp32, small) ----------------
__global__ void eproj_kernel(const float* __restrict__ qkv, const float* __restrict__ E,
                             float* __restrict__ kvp)
{
    int z = blockIdx.x;
    int b = z >> 1, kv = z & 1;
    int i = b >> 3, h = b & 7;
    const float* src = qkv + (size_t)i * T2 * LDQKV + h * DH + DIMD + kv * DIMD;
    float* dst = kvp + (size_t)b * 2 * KP * DH + (size_t)kv * KP * DH;

    __shared__ float ssrc[T2][DH];
    __shared__ float sE[T2][64];
    int half = blockIdx.y;

    for (int idx = threadIdx.x; idx < T2 * DH; idx += 256) {
        int j = idx >> 6, c = idx & 63;
        ssrc[j][c] = src[(size_t)j * LDQKV + c];
        sE[j][c]   = E[(size_t)j * KP + half * 64 + c];
    }
    __syncthreads();

    int c = threadIdx.x & 63;
    int kkq = threadIdx.x >> 6;
    float acc[16];
#pragma unroll
    for (int q = 0; q < 16; q++) acc[q] = 0.f;
    for (int j = 0; j < T2; j++) {
        float s = ssrc[j][c];
#pragma unroll
        for (int q = 0; q < 16; q++) acc[q] += s * sE[j][kkq * 16 + q];
    }
    int kk0 = half * 64 + kkq * 16;
#pragma unroll
    for (int q = 0; q < 16; q++) dst[(size_t)(kk0 + q) * DH + c] = acc[q];
}

// ---------------- Launch ----------------
static float* sym_addr(const void* s) {
    void* p = nullptr;
    cudaGetSymbolAddress(&p, s);
    return (float*)p;
}

extern "C" void kernel_launch(void* const* d_in, const int* in_sizes, int n_in,
                              void* d_out, int out_size)
{
    (void)in_sizes; (void)n_in; (void)out_size;
    const float* x      = (const float*)d_in[0];
    const float* Wqkv_t = (const float*)d_in[1];
    const float* Wo_t   = (const float*)d_in[2];
    const float* Wqkv_s = (const float*)d_in[3];
    const float* Wo_s   = (const float*)d_in[4];
    const float* E      = (const float*)d_in[5];
    const float* W1     = (const float*)d_in[6];
    const float* b1     = (const float*)d_in[7];
    const float* W2     = (const float*)d_in[8];
    const float* b2     = (const float*)d_in[9];
    float* out = (float*)d_out;

    float* xt  = sym_addr(g_xt);
    float* qkv = sym_addr(g_qkv);
    float* sc  = sym_addr(g_scores);
    float* att = sym_addr(g_attn);
    float* y1  = sym_addr(g_y1);
    float* ys  = sym_addr(g_ys);
    float* kvp = sym_addr(g_kvp);
    float* ffh = sym_addr(g_ffh);

    const float scale = 0.125f;  // 1/sqrt(64)

    // ---- temporal ----
    build_xt_kernel<<<NTOK1P, 128>>>(x, xt);

    // QKV temporal: M=16512 (padded), N=1536, K=512
    gemm_tc128<<<dim3(LDQKV / 128, NTOK1P / 128), 256>>>(
        xt, Wqkv_t, qkv, nullptr, nullptr, LDQKV, DIMD, 0);

    scores_tc<<<dim3(5, 5, B1 * HEADS), 256>>>(
        qkv,       LDQKV, (long)T1 * LDQKV, 64,
        qkv + 512, LDQKV, (long)T1 * LDQKV, 64,
        sc, T1, (long)8 * T1 * T1, (long)T1 * T1,
        T1, T1, scale);

    softmax_warp<<<(B1 * HEADS * T1 + 7) / 8, 256>>>(sc, T1, B1 * HEADS * T1);

    av_tc<<<dim3(1, 5, B1 * HEADS), 256>>>(
        sc, T1, (long)8 * T1 * T1, (long)T1 * T1,
        qkv + 1024, LDQKV, (long)T1 * LDQKV, 64,
        att, DIMD, (long)T1 * DIMD, 64,
        T1, T1);

    // y1 = att @ Wo_t + xt (padded rows of att are garbage -> only pad rows of y1)
    gemm_tc128<<<dim3(DIMD / 128, NTOK1P / 128), 256>>>(
        att, Wo_t, y1, nullptr, xt, DIMD, DIMD, 1);

    // ---- spatial ----
    build_ys_kernel<<<NTOK2, 128>>>(y1, ys);

    gemm_tc128<<<dim3(LDQKV / 128, NTOK2 / 128), 256>>>(
        ys, Wqkv_s, qkv, nullptr, nullptr, LDQKV, DIMD, 0);

    eproj_kernel<<<dim3(B2 * HEADS * 2, 2), 256>>>(qkv, E, kvp);

    scores_tc<<<dim3(2, 2, B2 * HEADS), 256>>>(
        qkv, LDQKV, (long)T2 * LDQKV, 64,
        kvp, DH, (long)8 * 2 * KP * DH, (long)2 * KP * DH,
        sc, KP, (long)8 * T2 * KP, (long)T2 * KP,
        T2, KP, scale);

    softmax_warp<<<(B2 * HEADS * T2 + 7) / 8, 256>>>(sc, KP, B2 * HEADS * T2);

    av_tc<<<dim3(1, 2, B2 * HEADS), 256>>>(
        sc, KP, (long)8 * T2 * KP, (long)T2 * KP,
        kvp + KP * DH, DH, (long)8 * 2 * KP * DH, (long)2 * KP * DH,
        att, DIMD, (long)T2 * DIMD, 64,
        T2, KP);

    gemm_tc128<<<dim3(DIMD / 128, NTOK2 / 128), 256>>>(
        att, Wo_s, out, nullptr, ys, DIMD, DIMD, 1);

    // ---- FFN ----
    gemm_tc128<<<dim3(DFF / 128, NTOK2 / 128), 256>>>(
        out, W1, ffh, b1, nullptr, DFF, DIMD, 2);

    gemm_tc128<<<dim3(DIMD / 128, NTOK2 / 128), 256>>>(
        ffh, W2, out, b2, out, DIMD, DFF, 3);
}

// round 16
// speedup vs baseline: 3.9087x; 2.1544x over previous
#include <cuda_runtime.h>
#include <cuda_bf16.h>
#include <mma.h>
#include <math.h>
#include <stdint.h>

using namespace nvcuda;
typedef __nv_bfloat16 bf16;

// ---------------- Problem constants ----------------
#define PATCHES 64
#define DIMD    512
#define HEADS   8
#define DH      64
#define DFF     1024
#define KP      128
#define T1      257
#define B1      64
#define T2      65
#define B2      256
#define NTOK1   (B1*T1)      // 16448
#define NTOK1P  16512        // 129*128
#define NTOK2   (B2*T2)      // 16640
#define LDQKV   (3*DIMD)     // 1536
#define MP1     320          // padded temporal P rows
#define LP1     288          // padded temporal P cols (9*32)
#define MP2     128          // padded spatial P rows
#define LP2     128          // spatial P cols

// ---------------- Scratch (device globals) --------
__device__ float g_xt[NTOK1P*DIMD];
__device__ bf16  b_xt[NTOK1P*DIMD];
__device__ bf16  b_qkv[(NTOK2+128)*LDQKV];          // oversized for guard-free tile reads
__device__ float g_scores[B1*HEADS*T1*T1];
__device__ bf16  b_P[(size_t)B1*HEADS*MP1*LP1];     // 512*320*288 (>= spatial 2048*128*128)
__device__ bf16  b_att[NTOK2*DIMD];
__device__ float g_y1[NTOK1P*DIMD];
__device__ float g_ys[NTOK2*DIMD];
__device__ bf16  b_ys[NTOK2*DIMD];
__device__ bf16  b_kvp[B2*HEADS*2*KP*DH];
__device__ bf16  b_ffh[NTOK2*DFF];
__device__ bf16  b_out[NTOK2*DIMD];
// bf16 weights
__device__ bf16 w_qkv_t[DIMD*LDQKV];
__device__ bf16 w_o_t[DIMD*DIMD];
__device__ bf16 w_qkv_s[DIMD*LDQKV];
__device__ bf16 w_o_s[DIMD*DIMD];
__device__ bf16 w_1[DIMD*DFF];
__device__ bf16 w_2[DFF*DIMD];
__device__ bf16 w_E[(T2)*KP];

__device__ __forceinline__ float gelu_exact(float v) {
    return 0.5f * v * (1.0f + erff(v * 0.70710678118654752f));
}

// ---------------- cp.async helpers ----------------
__device__ __forceinline__ void cp16(void* dst, const void* src) {
    uint32_t d = (uint32_t)__cvta_generic_to_shared(dst);
    asm volatile("cp.async.cg.shared.global [%0], [%1], 16;\n" :: "r"(d), "l"(src));
}
__device__ __forceinline__ void cp_commit() {
    asm volatile("cp.async.commit_group;\n");
}
template <int NW>
__device__ __forceinline__ void cp_wait() {
    asm volatile("cp.async.wait_group %0;\n" :: "n"(NW));
}

// ---------------- fp32 -> bf16 convert ----------------
__global__ void f2b_kernel(const float* __restrict__ src, bf16* __restrict__ dst, int n4) {
    int i = blockIdx.x * 256 + threadIdx.x;
    if (i >= n4) return;
    float4 v = ((const float4*)src)[i];
    __nv_bfloat162* d = (__nv_bfloat162*)(dst + (size_t)i * 4);
    d[0] = __nv_bfloat162{__float2bfloat16(v.x), __float2bfloat16(v.y)};
    d[1] = __nv_bfloat162{__float2bfloat16(v.z), __float2bfloat16(v.w)};
}

// ---------------- Rearrange kernels ----------------
__global__ void build_xt_kernel(const float* __restrict__ x, float* __restrict__ xt,
                                bf16* __restrict__ xtb) {
    int token = blockIdx.x;
    size_t doff = (size_t)token * DIMD + threadIdx.x * 4;
    int s = token / T1, t = token % T1;
    float4 v;
    if (s >= B1) v = make_float4(0.f, 0.f, 0.f, 0.f);
    else {
        size_t src_tok = (t == 0) ? 0 : (size_t)(1 + (size_t)(t - 1) * PATCHES + s);
        v = *(const float4*)(x + src_tok * DIMD + threadIdx.x * 4);
    }
    *(float4*)(xt + doff) = v;
    __nv_bfloat162* d = (__nv_bfloat162*)(xtb + doff);
    d[0] = __nv_bfloat162{__float2bfloat16(v.x), __float2bfloat16(v.y)};
    d[1] = __nv_bfloat162{__float2bfloat16(v.z), __float2bfloat16(v.w)};
}

__global__ void build_ys_kernel(const float* __restrict__ y1, float* __restrict__ ys,
                                bf16* __restrict__ ysb) {
    int token = blockIdx.x;
    int i = token / T2, j = token % T2;
    size_t src_tok = (j == 0) ? (size_t)(i % 64) * T1
                              : (size_t)(j - 1) * T1 + 1 + i;
    float4 v = *(const float4*)(y1 + src_tok * DIMD + threadIdx.x * 4);
    size_t doff = (size_t)token * DIMD + threadIdx.x * 4;
    *(float4*)(ys + doff) = v;
    __nv_bfloat162* d = (__nv_bfloat162*)(ysb + doff);
    d[0] = __nv_bfloat162{__float2bfloat16(v.x), __float2bfloat16(v.y)};
    d[1] = __nv_bfloat162{__float2bfloat16(v.z), __float2bfloat16(v.w)};
}

// ================= bf16 dense GEMM: 128x128, BK=32, cp.async 2-stage =========
#define EPI_R    1
#define EPI_BIAS 2
#define EPI_GELU 4
#define EPI_F32  8
#define EPI_B16  16

#define ALDb 40     // 32+8 bf16 (80B rows)
#define BLDb 136    // 128+8 bf16 (272B rows)
#define PLD  20     // float patch ld (80B)

__global__ void __launch_bounds__(256, 2)
gemm_bf128(const bf16* __restrict__ A, const bf16* __restrict__ B,
           float* __restrict__ Cf, bf16* __restrict__ Cb,
           const float* __restrict__ bias, const float* __restrict__ R,
           int N, int K, int epi)
{
    __shared__ __align__(16) bf16 sA[2][128 * ALDb];
    __shared__ __align__(16) bf16 sB[2][32 * BLDb];

    int tid = threadIdx.x;
    int warp = tid >> 5, lane = tid & 31;
    int wm = warp >> 2, wn = warp & 3;          // 2x4 warp grid, warp tile 64x32
    int row0 = blockIdx.y * 128;
    int col0 = blockIdx.x * 128;

    const bf16* Aptr = A + (size_t)row0 * K;
    const bf16* Bptr = B + col0;

    wmma::fragment<wmma::accumulator, 16, 16, 16, float> acc[4][2];
#pragma unroll
    for (int i = 0; i < 4; i++)
#pragma unroll
        for (int j = 0; j < 2; j++) wmma::fill_fragment(acc[i][j], 0.f);

    // A tile 128x32 bf16: 512 16B-chunks -> 2/thread: r=idx>>2, c8=idx&3
    // B tile 32x128 bf16: 512 16B-chunks -> 2/thread: r=idx>>4, c8=idx&15
    const int a_r0 = (tid      ) >> 2, a_c0 = (tid      ) & 3;
    const int a_r1 = (tid + 256) >> 2, a_c1 = (tid + 256) & 3;
    const int b_r0 = (tid      ) >> 4, b_c0 = (tid      ) & 15;
    const int b_r1 = (tid + 256) >> 4, b_c1 = (tid + 256) & 15;

    const int nch = K >> 5;

    cp16(&sA[0][a_r0 * ALDb + a_c0 * 8], Aptr + (size_t)a_r0 * K + a_c0 * 8);
    cp16(&sA[0][a_r1 * ALDb + a_c1 * 8], Aptr + (size_t)a_r1 * K + a_c1 * 8);
    cp16(&sB[0][b_r0 * BLDb + b_c0 * 8], Bptr + (size_t)b_r0 * N + b_c0 * 8);
    cp16(&sB[0][b_r1 * BLDb + b_c1 * 8], Bptr + (size_t)b_r1 * N + b_c1 * 8);
    cp_commit();

    for (int it = 0; it < nch; it++) {
        int buf = it & 1;
        if (it + 1 < nch) {
            int k0 = (it + 1) * 32;
            int nb = buf ^ 1;
            cp16(&sA[nb][a_r0 * ALDb + a_c0 * 8], Aptr + (size_t)a_r0 * K + k0 + a_c0 * 8);
            cp16(&sA[nb][a_r1 * ALDb + a_c1 * 8], Aptr + (size_t)a_r1 * K + k0 + a_c1 * 8);
            cp16(&sB[nb][b_r0 * BLDb + b_c0 * 8], Bptr + (size_t)(k0 + b_r0) * N + b_c0 * 8);
            cp16(&sB[nb][b_r1 * BLDb + b_c1 * 8], Bptr + (size_t)(k0 + b_r1) * N + b_c1 * 8);
            cp_commit();
            cp_wait<1>();
        } else {
            cp_wait<0>();
        }
        __syncthreads();

#pragma unroll
        for (int ks = 0; ks < 2; ks++) {
            wmma::fragment<wmma::matrix_a, 16, 16, 16, bf16, wmma::row_major> af[4];
            wmma::fragment<wmma::matrix_b, 16, 16, 16, bf16, wmma::row_major> bf_[2];
#pragma unroll
            for (int i = 0; i < 4; i++)
                wmma::load_matrix_sync(af[i], &sA[buf][(wm * 64 + i * 16) * ALDb + ks * 16], ALDb);
#pragma unroll
            for (int j = 0; j < 2; j++)
                wmma::load_matrix_sync(bf_[j], &sB[buf][(ks * 16) * BLDb + wn * 32 + j * 16], BLDb);
#pragma unroll
            for (int i = 0; i < 4; i++)
#pragma unroll
                for (int j = 0; j < 2; j++)
                    wmma::mma_sync(acc[i][j], af[i], bf_[j], acc[i][j]);
        }
        __syncthreads();
    }

    // epilogue: per-warp 16x16 patch (reuse sA as float scratch)
    float* patch = reinterpret_cast<float*>(&sA[0][0]) + warp * 16 * PLD;
    int pr = lane >> 1;
    int pc = (lane & 1) * 8;
#pragma unroll
    for (int i = 0; i < 4; i++) {
#pragma unroll
        for (int j = 0; j < 2; j++) {
            wmma::store_matrix_sync(patch, acc[i][j], PLD, wmma::mem_row_major);
            __syncwarp();
            int grow = row0 + wm * 64 + i * 16 + pr;
            int gcol = col0 + wn * 32 + j * 16 + pc;
#pragma unroll
            for (int h = 0; h < 2; h++) {
                float4 v = *(float4*)&patch[pr * PLD + pc + h * 4];
                size_t off = (size_t)grow * N + gcol + h * 4;
                if (epi & EPI_BIAS) {
                    float4 bb = *(const float4*)&bias[gcol + h * 4];
                    v.x += bb.x; v.y += bb.y; v.z += bb.z; v.w += bb.w;
                }
                if (epi & EPI_GELU) {
                    v.x = gelu_exact(v.x); v.y = gelu_exact(v.y);
                    v.z = gelu_exact(v.z); v.w = gelu_exact(v.w);
                }
                if (epi & EPI_R) {
                    float4 rr = *(const float4*)&R[off];
                    v.x += rr.x; v.y += rr.y; v.z += rr.z; v.w += rr.w;
                }
                if (epi & EPI_F32) *(float4*)&Cf[off] = v;
                if (epi & EPI_B16) {
                    __nv_bfloat162* d = (__nv_bfloat162*)(Cb + off);
                    d[0] = __nv_bfloat162{__float2bfloat16(v.x), __float2bfloat16(v.y)};
                    d[1] = __nv_bfloat162{__float2bfloat16(v.z), __float2bfloat16(v.w)};
                }
            }
            __syncwarp();
        }
    }
}

// ================= bf16 batched NT scores: C = scale * A(Mx64) * B(Nx64)^T ===
// guard-free tile loads (caller guarantees address validity); guarded stores.
#define QLD 72     // 64+8 bf16
#define OLD 68     // float out staging ld
__global__ void scores_bf(const bf16* __restrict__ Ab, int lda, long sao, long sai,
                          const bf16* __restrict__ Bb, int ldb, long sbo, long sbi,
                          float* __restrict__ Cb_, int ldc, long sco, long sci,
                          int M, int N, float scale)
{
    __shared__ __align__(16) bf16 sQ[64 * QLD];
    __shared__ __align__(16) bf16 sK[64 * QLD];
    __shared__ float sOut[64 * OLD];

    int z = blockIdx.z, zo = z >> 3, zi = z & 7;
    const bf16* A = Ab + (size_t)zo * sao + (size_t)zi * sai;
    const bf16* B = Bb + (size_t)zo * sbo + (size_t)zi * sbi;
    float* C = Cb_ + (size_t)zo * sco + (size_t)zi * sci;

    int tid = threadIdx.x;
    int warp = tid >> 5;
    int wm = warp >> 1, wn = warp & 1;       // 4x2, warp tile 16x32
    int row0 = blockIdx.y * 64;
    int col0 = blockIdx.x * 64;

    // 64x64 bf16 tiles: 512 16B-chunks each; 2/thread
#pragma unroll
    for (int l = 0; l < 2; l++) {
        int idx = tid + l * 256;
        int r = idx >> 3, c8 = idx & 7;
        *(float4*)&sQ[r * QLD + c8 * 8] = *(const float4*)(A + (size_t)(row0 + r) * lda + c8 * 8);
        *(float4*)&sK[r * QLD + c8 * 8] = *(const float4*)(B + (size_t)(col0 + r) * ldb + c8 * 8);
    }
    __syncthreads();

    wmma::fragment<wmma::accumulator, 16, 16, 16, float> c0, c1;
    wmma::fill_fragment(c0, 0.f);
    wmma::fill_fragment(c1, 0.f);
#pragma unroll
    for (int kk = 0; kk < 64; kk += 16) {
        wmma::fragment<wmma::matrix_a, 16, 16, 16, bf16, wmma::row_major> a;
        wmma::fragment<wmma::matrix_b, 16, 16, 16, bf16, wmma::col_major> b0, b1;
        wmma::load_matrix_sync(a, &sQ[(wm * 16) * QLD + kk], QLD);
        wmma::load_matrix_sync(b0, &sK[(wn * 32) * QLD + kk], QLD);
        wmma::load_matrix_sync(b1, &sK[(wn * 32 + 16) * QLD + kk], QLD);
        wmma::mma_sync(c0, a, b0, c0);
        wmma::mma_sync(c1, a, b1, c1);
    }
    __syncthreads();

    wmma::store_matrix_sync(&sOut[(wm * 16) * OLD + wn * 32], c0, OLD, wmma::mem_row_major);
    wmma::store_matrix_sync(&sOut[(wm * 16) * OLD + wn * 32 + 16], c1, OLD, wmma::mem_row_major);
    __syncthreads();

    for (int idx = tid; idx < 64 * 64; idx += 256) {
        int r = idx >> 6, c = idx & 63;
        if (row0 + r < M && col0 + c < N)
            C[(size_t)(row0 + r) * ldc + col0 + c] = sOut[r * OLD + c] * scale;
    }
}

// ================= bf16 batched AV: C(Mx64) = P(64-tile x LPx) * V =========
// guard-free loads; rows >= M produce garbage that is never stored.
#define PLDb 40    // 32+8
__global__ void av_bf(const bf16* __restrict__ Pb, int LPx, long sPz,
                      const bf16* __restrict__ Vb, int ldv, long svo, long svi,
                      bf16* __restrict__ Cb_, int ldc, long sco, long sci,
                      int M, int nch)
{
    __shared__ __align__(16) bf16 sP[64 * PLDb];
    __shared__ __align__(16) bf16 sV[32 * QLD];
    __shared__ float sOut[64 * OLD];

    int z = blockIdx.z, zo = z >> 3, zi = z & 7;
    const bf16* P = Pb + (size_t)z * sPz;
    const bf16* V = Vb + (size_t)zo * svo + (size_t)zi * svi;
    bf16* C = Cb_ + (size_t)zo * sco + (size_t)zi * sci;

    int tid = threadIdx.x;
    int warp = tid >> 5;
    int wm = warp >> 1, wn = warp & 1;
    int row0 = blockIdx.y * 64;

    wmma::fragment<wmma::accumulator, 16, 16, 16, float> c0, c1;
    wmma::fill_fragment(c0, 0.f);
    wmma::fill_fragment(c1, 0.f);

    for (int it = 0; it < nch; it++) {
        int k0 = it * 32;
        // P tile 64x32: 256 chunks, 1/thread: r=tid>>2, c8=tid&3
        {
            int r = tid >> 2, c8 = tid & 3;
            *(float4*)&sP[r * PLDb + c8 * 8] = *(const float4*)(P + (size_t)(row0 + r) * LPx + k0 + c8 * 8);
        }
        // V tile 32x64: 256 chunks, 1/thread: r=tid>>3, c8=tid&7
        {
            int r = tid >> 3, c8 = tid & 7;
            *(float4*)&sV[r * QLD + c8 * 8] = *(const float4*)(V + (size_t)(k0 + r) * ldv + c8 * 8);
        }
        __syncthreads();
#pragma unroll
        for (int ks = 0; ks < 2; ks++) {
            wmma::fragment<wmma::matrix_a, 16, 16, 16, bf16, wmma::row_major> a;
            wmma::fragment<wmma::matrix_b, 16, 16, 16, bf16, wmma::row_major> b0, b1;
            wmma::load_matrix_sync(a, &sP[(wm * 16) * PLDb + ks * 16], PLDb);
            wmma::load_matrix_sync(b0, &sV[(ks * 16) * QLD + wn * 32], QLD);
            wmma::load_matrix_sync(b1, &sV[(ks * 16) * QLD + wn * 32 + 16], QLD);
            wmma::mma_sync(c0, a, b0, c0);
            wmma::mma_sync(c1, a, b1, c1);
        }
        __syncthreads();
    }

    wmma::store_matrix_sync(&sOut[(wm * 16) * OLD + wn * 32], c0, OLD, wmma::mem_row_major);
    wmma::store_matrix_sync(&sOut[(wm * 16) * OLD + wn * 32 + 16], c1, OLD, wmma::mem_row_major);
    __syncthreads();

    for (int idx = tid; idx < 64 * 64; idx += 256) {
        int r = idx >> 6, c = idx & 63;
        if (row0 + r < M)
            C[(size_t)(row0 + r) * ldc + c] = __float2bfloat16(sOut[r * OLD + c]);
    }
}

// ---------------- Warp-per-row softmax: fp32 scores -> bf16 padded P --------
__global__ void softmax_bf(const float* __restrict__ S, int L,
                           bf16* __restrict__ P, int LPx, int Mreal, long sPz,
                           int rows)
{
    int row = blockIdx.x * 8 + (threadIdx.x >> 5);
    if (row >= rows) return;
    int lane = threadIdx.x & 31;
    const float* src = S + (size_t)row * L;
    int z = row / Mreal, m = row % Mreal;
    bf16* dst = P + (size_t)z * sPz + (size_t)m * LPx;

    float mx = -1e30f;
    for (int i = lane; i < L; i += 32) mx = fmaxf(mx, src[i]);
#pragma unroll
    for (int s = 16; s > 0; s >>= 1) mx = fmaxf(mx, __shfl_xor_sync(0xffffffffu, mx, s));

    float sum = 0.f;
    for (int i = lane; i < L; i += 32) sum += __expf(src[i] - mx);
#pragma unroll
    for (int s = 16; s > 0; s >>= 1) sum += __shfl_xor_sync(0xffffffffu, sum, s);

    float inv = 1.f / sum;
    for (int i = lane; i < L; i += 32)
        dst[i] = __float2bfloat16(__expf(src[i] - mx) * inv);
    for (int i = L + lane; i < LPx; i += 32)
        dst[i] = __float2bfloat16(0.f);
}

// ---------------- Linformer E-projection (bf16 in/out, fp32 accum) ----------
__global__ void eproj_bf(const bf16* __restrict__ qkv, const bf16* __restrict__ E,
                         bf16* __restrict__ kvp)
{
    int z = blockIdx.x;
    int b = z >> 1, kv = z & 1;
    int i = b >> 3, h = b & 7;
    const bf16* src = qkv + (size_t)i * T2 * LDQKV + h * DH + DIMD + kv * DIMD;
    bf16* dst = kvp + (size_t)b * 2 * KP * DH + (size_t)kv * KP * DH;

    __shared__ float ssrc[T2][DH];
    __shared__ float sE[T2][64];
    int half = blockIdx.y;

    for (int idx = threadIdx.x; idx < T2 * DH; idx += 256) {
        int j = idx >> 6, c = idx & 63;
        ssrc[j][c] = __bfloat162float(src[(size_t)j * LDQKV + c]);
        sE[j][c]   = __bfloat162float(E[(size_t)j * KP + half * 64 + c]);
    }
    __syncthreads();

    int c = threadIdx.x & 63;
    int kkq = threadIdx.x >> 6;
    float acc[16];
#pragma unroll
    for (int q = 0; q < 16; q++) acc[q] = 0.f;
    for (int j = 0; j < T2; j++) {
        float s = ssrc[j][c];
#pragma unroll
        for (int q = 0; q < 16; q++) acc[q] += s * sE[j][kkq * 16 + q];
    }
    int kk0 = half * 64 + kkq * 16;
#pragma unroll
    for (int q = 0; q < 16; q++) dst[(size_t)(kk0 + q) * DH + c] = __float2bfloat16(acc[q]);
}

// ---------------- Launch ----------------
template <typename T>
static T* sym_addr(const void* s) {
    void* p = nullptr;
    cudaGetSymbolAddress(&p, s);
    return (T*)p;
}

static void conv(const float* src, bf16* dst, int n) {
    f2b_kernel<<<(n / 4 + 255) / 256, 256>>>(src, dst, n / 4);
}

extern "C" void kernel_launch(void* const* d_in, const int* in_sizes, int n_in,
                              void* d_out, int out_size)
{
    (void)in_sizes; (void)n_in; (void)out_size;
    const float* x      = (const float*)d_in[0];
    const float* Wqkv_t = (const float*)d_in[1];
    const float* Wo_t   = (const float*)d_in[2];
    const float* Wqkv_s = (const float*)d_in[3];
    const float* Wo_s   = (const float*)d_in[4];
    const float* E      = (const float*)d_in[5];
    const float* W1     = (const float*)d_in[6];
    const float* b1     = (const float*)d_in[7];
    const float* W2     = (const float*)d_in[8];
    const float* b2     = (const float*)d_in[9];
    float* out = (float*)d_out;

    float* xt   = sym_addr<float>(g_xt);
    bf16*  xtb  = sym_addr<bf16>(b_xt);
    bf16*  qkv  = sym_addr<bf16>(b_qkv);
    float* sc   = sym_addr<float>(g_scores);
    bf16*  P    = sym_addr<bf16>(b_P);
    bf16*  att  = sym_addr<bf16>(b_att);
    float* y1   = sym_addr<float>(g_y1);
    float* ys   = sym_addr<float>(g_ys);
    bf16*  ysb  = sym_addr<bf16>(b_ys);
    bf16*  kvp  = sym_addr<bf16>(b_kvp);
    bf16*  ffh  = sym_addr<bf16>(b_ffh);
    bf16*  outb = sym_addr<bf16>(b_out);
    bf16*  wqt  = sym_addr<bf16>(w_qkv_t);
    bf16*  wot  = sym_addr<bf16>(w_o_t);
    bf16*  wqs  = sym_addr<bf16>(w_qkv_s);
    bf16*  wos  = sym_addr<bf16>(w_o_s);
    bf16*  w1b  = sym_addr<bf16>(w_1);
    bf16*  w2b  = sym_addr<bf16>(w_2);
    bf16*  wEb  = sym_addr<bf16>(w_E);

    const float scale = 0.125f;

    // ---- weight conversion ----
    conv(Wqkv_t, wqt, DIMD * LDQKV);
    conv(Wo_t,   wot, DIMD * DIMD);
    conv(Wqkv_s, wqs, DIMD * LDQKV);
    conv(Wo_s,   wos, DIMD * DIMD);
    conv(W1,     w1b, DIMD * DFF);
    conv(W2,     w2b, DFF * DIMD);
    conv(E,      wEb, T2 * KP);

    // ---- temporal ----
    build_xt_kernel<<<NTOK1P, 128>>>(x, xt, xtb);

    gemm_bf128<<<dim3(LDQKV / 128, NTOK1P / 128), 256>>>(
        xtb, wqt, nullptr, qkv, nullptr, nullptr, LDQKV, DIMD, EPI_B16);

    scores_bf<<<dim3(5, 5, B1 * HEADS), 256>>>(
        qkv,       LDQKV, (long)T1 * LDQKV, 64,
        qkv + 512, LDQKV, (long)T1 * LDQKV, 64,
        sc, T1, (long)8 * T1 * T1, (long)T1 * T1,
        T1, T1, scale);

    softmax_bf<<<(B1 * HEADS * T1 + 7) / 8, 256>>>(
        sc, T1, P, LP1, T1, (long)MP1 * LP1, B1 * HEADS * T1);

    av_bf<<<dim3(1, 5, B1 * HEADS), 256>>>(
        P, LP1, (long)MP1 * LP1,
        qkv + 1024, LDQKV, (long)T1 * LDQKV, 64,
        att, DIMD, (long)T1 * DIMD, 64,
        T1, LP1 / 32);

    gemm_bf128<<<dim3(DIMD / 128, NTOK1P / 128), 256>>>(
        att, wot, y1, nullptr, nullptr, xt, DIMD, DIMD, EPI_R | EPI_F32);

    // ---- spatial ----
    build_ys_kernel<<<NTOK2, 128>>>(y1, ys, ysb);

    gemm_bf128<<<dim3(LDQKV / 128, NTOK2 / 128), 256>>>(
        ysb, wqs, nullptr, qkv, nullptr, nullptr, LDQKV, DIMD, EPI_B16);

    eproj_bf<<<dim3(B2 * HEADS * 2, 2), 256>>>(qkv, wEb, kvp);

    scores_bf<<<dim3(2, 2, B2 * HEADS), 256>>>(
        qkv, LDQKV, (long)T2 * LDQKV, 64,
        kvp, DH, (long)8 * 2 * KP * DH, (long)2 * KP * DH,
        sc, KP, (long)8 * T2 * KP, (long)T2 * KP,
        T2, KP, scale);

    softmax_bf<<<(B2 * HEADS * T2 + 7) / 8, 256>>>(
        sc, KP, P, LP2, T2, (long)MP2 * LP2, B2 * HEADS * T2);

    av_bf<<<dim3(1, 2, B2 * HEADS), 256>>>(
        P, LP2, (long)MP2 * LP2,
        kvp + KP * DH, DH, (long)8 * 2 * KP * DH, (long)2 * KP * DH,
        att, DIMD, (long)T2 * DIMD, 64,
        T2, LP2 / 32);

    gemm_bf128<<<dim3(DIMD / 128, NTOK2 / 128), 256>>>(
        att, wos, out, outb, nullptr, ys, DIMD, DIMD, EPI_R | EPI_F32 | EPI_B16);

    // ---- FFN ----
    gemm_bf128<<<dim3(DFF / 128, NTOK2 / 128), 256>>>(
        outb, w1b, nullptr, ffh, b1, nullptr, DFF, DIMD, EPI_BIAS | EPI_GELU | EPI_B16);

    gemm_bf128<<<dim3(DIMD / 128, NTOK2 / 128), 256>>>(
        ffh, w2b, out, nullptr, b2, out, DIMD, DFF, EPI_BIAS | EPI_R | EPI_F32);
}